// round 5
// baseline (speedup 1.0000x reference)
#include <cuda_runtime.h>
#include <math.h>

// Problem constants (fixed by the reference)
#define BB 4
#define TT 2048
#define CC 1024
#define HH 16
#define HD 64

// Scratch: q,k,v in [B,H,T,HD] layout, y in [B,T,C] layout.
__device__ float g_q[(size_t)BB * HH * TT * HD];
__device__ float g_k[(size_t)BB * HH * TT * HD];
__device__ float g_v[(size_t)BB * HH * TT * HD];
__device__ float g_y[(size_t)BB * TT * CC];

// ---------------------------------------------------------------------------
// GEMM: out = A[M,K] @ W[N,K]^T + bias   (torch Linear convention)
// MODE 0: out row-major [M,N]
// MODE 1: out scattered to [B,H,T,HD]  (m = b*T+t, n = h*HD+d)
// Tiles: 128x128x16, 256 threads, 8x8 per thread.
// ---------------------------------------------------------------------------
template <int MODE>
__global__ void __launch_bounds__(256)
gemm_bias(const float* __restrict__ A, const float* __restrict__ W,
          const float* __restrict__ bias, float* __restrict__ out,
          int M, int N, int K)
{
    __shared__ float As[16][132];
    __shared__ float Bs[16][132];

    const int tid = threadIdx.x;
    const int bm = blockIdx.y * 128;
    const int bn = blockIdx.x * 128;
    const int tx = tid & 15;   // 0..15  -> 8 cols each
    const int ty = tid >> 4;   // 0..15  -> 8 rows each
    const int lrow = tid >> 2; // 0..63
    const int lc4 = tid & 3;   // which float4 in the 16-wide K slice

    float acc[8][8];
#pragma unroll
    for (int i = 0; i < 8; i++)
#pragma unroll
        for (int j = 0; j < 8; j++) acc[i][j] = 0.f;

    for (int k0 = 0; k0 < K; k0 += 16) {
#pragma unroll
        for (int i = 0; i < 2; i++) {
            int row = lrow + i * 64;
            float4 a4 = *(const float4*)&A[(size_t)(bm + row) * K + k0 + lc4 * 4];
            As[lc4 * 4 + 0][row] = a4.x;
            As[lc4 * 4 + 1][row] = a4.y;
            As[lc4 * 4 + 2][row] = a4.z;
            As[lc4 * 4 + 3][row] = a4.w;
            float4 b4 = *(const float4*)&W[(size_t)(bn + row) * K + k0 + lc4 * 4];
            Bs[lc4 * 4 + 0][row] = b4.x;
            Bs[lc4 * 4 + 1][row] = b4.y;
            Bs[lc4 * 4 + 2][row] = b4.z;
            Bs[lc4 * 4 + 3][row] = b4.w;
        }
        __syncthreads();

#pragma unroll
        for (int kk = 0; kk < 16; kk++) {
            float4 a0 = *(const float4*)&As[kk][ty * 8];
            float4 a1 = *(const float4*)&As[kk][ty * 8 + 4];
            float4 b0 = *(const float4*)&Bs[kk][tx * 8];
            float4 b1 = *(const float4*)&Bs[kk][tx * 8 + 4];
            float af[8] = {a0.x, a0.y, a0.z, a0.w, a1.x, a1.y, a1.z, a1.w};
            float bf[8] = {b0.x, b0.y, b0.z, b0.w, b1.x, b1.y, b1.z, b1.w};
#pragma unroll
            for (int i = 0; i < 8; i++)
#pragma unroll
                for (int j = 0; j < 8; j++) acc[i][j] += af[i] * bf[j];
        }
        __syncthreads();
    }

#pragma unroll
    for (int i = 0; i < 8; i++) {
        int m = bm + ty * 8 + i;
#pragma unroll
        for (int j = 0; j < 8; j += 4) {
            int n = bn + tx * 8 + j;
            float4 r;
            r.x = acc[i][j + 0] + bias[n + 0];
            r.y = acc[i][j + 1] + bias[n + 1];
            r.z = acc[i][j + 2] + bias[n + 2];
            r.w = acc[i][j + 3] + bias[n + 3];
            if (MODE == 0) {
                *(float4*)&out[(size_t)m * N + n] = r;
            } else {
                int b = m >> 11;          // /T (T=2048)
                int t = m & (TT - 1);
                int h = n >> 6;           // /HD
                int d = n & (HD - 1);
                *(float4*)&out[((size_t)(b * HH + h) * TT + t) * HD + d] = r;
            }
        }
    }
}

// ---------------------------------------------------------------------------
// Flash attention (causal + padding mask), fp32, online softmax.
// Grid: (T/128, B*H). 128 threads; each thread owns one query row.
// k/v tiles of 64 rows staged in smem; reads are warp-broadcast.
// ---------------------------------------------------------------------------
__global__ void __launch_bounds__(128)
attn_kernel(const float* __restrict__ q, const float* __restrict__ k,
            const float* __restrict__ v, const int* __restrict__ mask,
            float* __restrict__ y)
{
    const int bh = blockIdx.y;
    const int b = bh >> 4;       // /H
    const int h = bh & (HH - 1);
    const int q0 = blockIdx.x * 128;
    const int tid = threadIdx.x;
    const int qi = q0 + tid;

    __shared__ float ks[64 * HD];
    __shared__ float vs[64 * HD];
    __shared__ int ms[64];

    float qr[HD];
    const float* qptr = q + ((size_t)bh * TT + qi) * HD;
#pragma unroll
    for (int d = 0; d < HD; d += 4) {
        float4 t4 = *(const float4*)(qptr + d);
        qr[d] = t4.x; qr[d + 1] = t4.y; qr[d + 2] = t4.z; qr[d + 3] = t4.w;
    }

    float mrow = -INFINITY;
    float lrow = 0.f;
    float acc[HD];
#pragma unroll
    for (int d = 0; d < HD; d++) acc[d] = 0.f;

    const int jend = q0 + 127;  // last kv position any row in block needs
    for (int j0 = 0; j0 <= jend; j0 += 64) {
        // cooperative tile load: 64*64 floats = 1024 float4, 8 per thread
        const float* kbase = k + ((size_t)bh * TT + j0) * HD;
        const float* vbase = v + ((size_t)bh * TT + j0) * HD;
#pragma unroll
        for (int i = 0; i < 8; i++) {
            int fid = tid + i * 128;
            *(float4*)&ks[fid * 4] = *(const float4*)&kbase[fid * 4];
            *(float4*)&vs[fid * 4] = *(const float4*)&vbase[fid * 4];
        }
        if (tid < 64) ms[tid] = mask[b * TT + j0 + tid];
        __syncthreads();

        int jmax = qi - j0;
        if (jmax > 63) jmax = 63;
        for (int j = 0; j <= jmax; j++) {
            if (ms[j] == 0) continue;
            const float* kr = &ks[j * HD];
            float s0 = 0.f, s1 = 0.f, s2 = 0.f, s3 = 0.f;
#pragma unroll
            for (int d = 0; d < HD; d += 16) {
                float4 k0 = *(const float4*)&kr[d];
                float4 k1 = *(const float4*)&kr[d + 4];
                float4 k2 = *(const float4*)&kr[d + 8];
                float4 k3 = *(const float4*)&kr[d + 12];
                s0 += qr[d + 0] * k0.x + qr[d + 1] * k0.y + qr[d + 2] * k0.z + qr[d + 3] * k0.w;
                s1 += qr[d + 4] * k1.x + qr[d + 5] * k1.y + qr[d + 6] * k1.z + qr[d + 7] * k1.w;
                s2 += qr[d + 8] * k2.x + qr[d + 9] * k2.y + qr[d + 10] * k2.z + qr[d + 11] * k2.w;
                s3 += qr[d + 12] * k3.x + qr[d + 13] * k3.y + qr[d + 14] * k3.z + qr[d + 15] * k3.w;
            }
            float s = ((s0 + s1) + (s2 + s3)) * 0.125f;  // 1/sqrt(64)

            const float* vr = &vs[j * HD];
            if (s <= mrow) {
                float p = __expf(s - mrow);
                lrow += p;
#pragma unroll
                for (int d = 0; d < HD; d += 4) {
                    float4 v4 = *(const float4*)&vr[d];
                    acc[d + 0] += p * v4.x;
                    acc[d + 1] += p * v4.y;
                    acc[d + 2] += p * v4.z;
                    acc[d + 3] += p * v4.w;
                }
            } else {
                float c = __expf(mrow - s);  // exp(-inf)=0 on first hit
                mrow = s;
                lrow = lrow * c + 1.f;
#pragma unroll
                for (int d = 0; d < HD; d += 4) {
                    float4 v4 = *(const float4*)&vr[d];
                    acc[d + 0] = acc[d + 0] * c + v4.x;
                    acc[d + 1] = acc[d + 1] * c + v4.y;
                    acc[d + 2] = acc[d + 2] * c + v4.z;
                    acc[d + 3] = acc[d + 3] * c + v4.w;
                }
            }
        }
        __syncthreads();
    }

    float inv = 1.f / lrow;
    float* yp = y + ((size_t)b * TT + qi) * CC + h * HD;
#pragma unroll
    for (int d = 0; d < HD; d += 4) {
        float4 o;
        o.x = acc[d + 0] * inv;
        o.y = acc[d + 1] * inv;
        o.z = acc[d + 2] * inv;
        o.w = acc[d + 3] * inv;
        *(float4*)(yp + d) = o;
    }
}

// ---------------------------------------------------------------------------
extern "C" void kernel_launch(void* const* d_in, const int* in_sizes, int n_in,
                              void* d_out, int out_size)
{
    const float* x  = (const float*)d_in[0];
    const float* Wq = (const float*)d_in[1];
    const float* bq = (const float*)d_in[2];
    const float* Wk = (const float*)d_in[3];
    const float* bk = (const float*)d_in[4];
    const float* Wv = (const float*)d_in[5];
    const float* bv = (const float*)d_in[6];
    const float* Wp = (const float*)d_in[7];
    const float* bp = (const float*)d_in[8];
    const int* mask = (const int*)d_in[9];
    float* out = (float*)d_out;

    float *qp, *kp, *vp, *yp;
    cudaGetSymbolAddress((void**)&qp, g_q);
    cudaGetSymbolAddress((void**)&kp, g_k);
    cudaGetSymbolAddress((void**)&vp, g_v);
    cudaGetSymbolAddress((void**)&yp, g_y);

    const int M = BB * TT;   // 8192
    const int N = CC;        // 1024
    const int K = CC;        // 1024
    dim3 gg(N / 128, M / 128);

    gemm_bias<1><<<gg, 256>>>(x, Wq, bq, qp, M, N, K);
    gemm_bias<1><<<gg, 256>>>(x, Wk, bk, kp, M, N, K);
    gemm_bias<1><<<gg, 256>>>(x, Wv, bv, vp, M, N, K);

    attn_kernel<<<dim3(TT / 128, BB * HH), 128>>>(qp, kp, vp, mask, yp);

    gemm_bias<0><<<gg, 256>>>(yp, Wp, bp, out, M, N, K);
}

// round 8
// speedup vs baseline: 1.6235x; 1.6235x over previous
#include <cuda_runtime.h>
#include <cuda_fp16.h>
#include <math.h>
#include <cstdint>

// Problem constants
#define BB 4
#define TT 2048
#define CC 1024
#define HH 16
#define HD 64
#define MM (BB * TT)   // 8192

// ---------------- scratch (device globals; no allocs allowed) ----------------
__device__ float  g_q[(size_t)MM * CC];   // [B,H,T,HD]
__device__ float  g_k[(size_t)MM * CC];
__device__ float  g_v[(size_t)MM * CC];
__device__ float  g_y[(size_t)MM * CC];   // [B,T,C]
__device__ __half g_xh[(size_t)MM * CC];
__device__ __half g_yh[(size_t)MM * CC];
__device__ __half g_wqh[(size_t)CC * CC];
__device__ __half g_wkh[(size_t)CC * CC];
__device__ __half g_wvh[(size_t)CC * CC];
__device__ __half g_wph[(size_t)CC * CC];

__device__ __forceinline__ uint32_t smem_to_u32(const void* p) {
    uint32_t a;
    asm("{ .reg .u64 t; cvta.to.shared.u64 t, %1; cvt.u32.u64 %0, t; }"
        : "=r"(a) : "l"(p));
    return a;
}

__device__ __forceinline__ void ldsm_x4(uint32_t addr, uint32_t& r0, uint32_t& r1,
                                        uint32_t& r2, uint32_t& r3) {
    asm volatile("ldmatrix.sync.aligned.m8n8.x4.shared.b16 {%0,%1,%2,%3}, [%4];"
                 : "=r"(r0), "=r"(r1), "=r"(r2), "=r"(r3) : "r"(addr));
}

__device__ __forceinline__ void mma16816(float* c, uint32_t a0, uint32_t a1,
                                         uint32_t a2, uint32_t a3,
                                         uint32_t b0, uint32_t b1) {
    asm volatile(
        "mma.sync.aligned.m16n8k16.row.col.f32.f16.f16.f32 "
        "{%0,%1,%2,%3}, {%4,%5,%6,%7}, {%8,%9}, {%0,%1,%2,%3};"
        : "+f"(c[0]), "+f"(c[1]), "+f"(c[2]), "+f"(c[3])
        : "r"(a0), "r"(a1), "r"(a2), "r"(a3), "r"(b0), "r"(b1));
}

// ---------------- fp32 -> fp16 conversion ----------------
__global__ void __launch_bounds__(256)
f2h_kernel(const float* __restrict__ in, __half* __restrict__ out, int n)
{
    int i = (blockIdx.x * 256 + threadIdx.x) * 4;
    if (i < n) {
        float4 v = *(const float4*)(in + i);
        reinterpret_cast<__half2*>(out + i)[0] = __floats2half2_rn(v.x, v.y);
        reinterpret_cast<__half2*>(out + i)[1] = __floats2half2_rn(v.z, v.w);
    }
}

// ---------------------------------------------------------------------------
// mma.sync fp16 GEMM: out = A[M,K] @ W[N,K]^T + bias
// MODE 0: out row-major [M,N].  MODE 1: out scattered to [B,H,T,HD].
// CTA tile 128x128, 8 warps (2m x 4n), warp tile 64x32, K staged by 32,
// double-buffered smem, padded stride 40 halfs (conflict-free ldmatrix).
// ---------------------------------------------------------------------------
#define RS 40                        // smem row stride in halfs
#define BUFB (128 * RS * 2)          // bytes per buffer (10240)

template <int MODE>
__global__ void __launch_bounds__(256)
gemm_mma(const __half* __restrict__ A, const __half* __restrict__ W,
         const float* __restrict__ bias, float* __restrict__ out,
         int M, int N, int K)
{
    __shared__ __half As[2][128 * RS];
    __shared__ __half Bs[2][128 * RS];

    const int tid = threadIdx.x;
    const int lid = tid & 31;
    const int wid = tid >> 5;
    const int bm = blockIdx.y * 128;
    const int bn = blockIdx.x * 128;
    const int wm = (wid >> 2) * 64;
    const int wn = (wid & 3) * 32;

    const uint32_t as_base = smem_to_u32(As);
    const uint32_t bs_base = smem_to_u32(Bs);

    float acc[4][4][4];
#pragma unroll
    for (int f = 0; f < 4; f++)
#pragma unroll
        for (int g = 0; g < 4; g++)
#pragma unroll
            for (int e = 0; e < 4; e++) acc[f][g][e] = 0.f;

    // gmem<->smem mapping: idx = tid (+256): row = idx/4, col = (idx&3)*8 halfs
    const int r0 = tid >> 2;
    const int c8 = (tid & 3) * 8;
    const uint32_t soff0 = (uint32_t)(r0 * RS + c8) * 2;
    const uint32_t soff1 = (uint32_t)((r0 + 64) * RS + c8) * 2;

    // ldmatrix per-thread byte offsets (within a buffer), kk adds 32 bytes
    uint32_t a_off[4], b_off[2];
#pragma unroll
    for (int f = 0; f < 4; f++) {
        int row = wm + f * 16 + (lid & 15);
        int ko  = ((lid >> 4) & 1) * 8;
        a_off[f] = (uint32_t)(row * RS + ko) * 2;
    }
#pragma unroll
    for (int p = 0; p < 2; p++) {
        int nrow = wn + p * 16 + ((lid >> 4) & 1) * 8 + (lid & 7);
        int ko   = ((lid >> 3) & 1) * 8;
        b_off[p] = (uint32_t)(nrow * RS + ko) * 2;
    }

    const int NS = K / 32;

    // preload stage 0
    {
        const __half* ag = A + (size_t)(bm + r0) * K + c8;
        const __half* wg = W + (size_t)(bn + r0) * K + c8;
        *(float4*)((char*)As[0] + soff0) = *(const float4*)ag;
        *(float4*)((char*)As[0] + soff1) = *(const float4*)(ag + (size_t)64 * K);
        *(float4*)((char*)Bs[0] + soff0) = *(const float4*)wg;
        *(float4*)((char*)Bs[0] + soff1) = *(const float4*)(wg + (size_t)64 * K);
    }
    __syncthreads();

#pragma unroll 1
    for (int s = 0; s < NS; s++) {
        const int buf = s & 1;
        float4 pa0, pa1, pb0, pb1;
        if (s + 1 < NS) {
            const int k0 = (s + 1) * 32;
            const __half* ag = A + (size_t)(bm + r0) * K + k0 + c8;
            const __half* wg = W + (size_t)(bn + r0) * K + k0 + c8;
            pa0 = *(const float4*)ag;
            pa1 = *(const float4*)(ag + (size_t)64 * K);
            pb0 = *(const float4*)wg;
            pb1 = *(const float4*)(wg + (size_t)64 * K);
        }

        const uint32_t ab = as_base + buf * BUFB;
        const uint32_t bb = bs_base + buf * BUFB;
#pragma unroll
        for (int kk = 0; kk < 2; kk++) {
            uint32_t a[4][4];
#pragma unroll
            for (int f = 0; f < 4; f++)
                ldsm_x4(ab + a_off[f] + kk * 32, a[f][0], a[f][1], a[f][2], a[f][3]);
            uint32_t b[2][4];
#pragma unroll
            for (int p = 0; p < 2; p++)
                ldsm_x4(bb + b_off[p] + kk * 32, b[p][0], b[p][1], b[p][2], b[p][3]);
#pragma unroll
            for (int f = 0; f < 4; f++)
#pragma unroll
                for (int g = 0; g < 4; g++)
                    mma16816(acc[f][g], a[f][0], a[f][1], a[f][2], a[f][3],
                             b[g >> 1][(g & 1) * 2], b[g >> 1][(g & 1) * 2 + 1]);
        }

        if (s + 1 < NS) {
            __syncthreads();
            const int nb = (s + 1) & 1;
            *(float4*)((char*)As[nb] + soff0) = pa0;
            *(float4*)((char*)As[nb] + soff1) = pa1;
            *(float4*)((char*)Bs[nb] + soff0) = pb0;
            *(float4*)((char*)Bs[nb] + soff1) = pb1;
            __syncthreads();
        }
    }

    // epilogue: acc frag (f,g): c0,c1 at (m, n..n+1), c2,c3 at (m+8, n..n+1)
#pragma unroll
    for (int f = 0; f < 4; f++) {
#pragma unroll
        for (int g = 0; g < 4; g++) {
            int m0 = bm + wm + f * 16 + (lid >> 2);
            int n0 = bn + wn + g * 8 + (lid & 3) * 2;
            float2 lo, hi;
            lo.x = acc[f][g][0] + bias[n0];
            lo.y = acc[f][g][1] + bias[n0 + 1];
            hi.x = acc[f][g][2] + bias[n0];
            hi.y = acc[f][g][3] + bias[n0 + 1];
            if (MODE == 0) {
                *(float2*)&out[(size_t)m0 * N + n0] = lo;
                *(float2*)&out[(size_t)(m0 + 8) * N + n0] = hi;
            } else {
                int b = m0 >> 11;
                int t = m0 & (TT - 1);
                int h = n0 >> 6;
                int d = n0 & (HD - 1);
                size_t base = ((size_t)(b * HH + h) * TT + t) * HD + d;
                *(float2*)&out[base] = lo;
                *(float2*)&out[base + (size_t)8 * HD] = hi;
            }
        }
    }
}

// ---------------------------------------------------------------------------
// Flash attention (causal + padding mask), fp32, online softmax.
// q/k/v in [B,H,T,HD]; y written to [B,T,C].
// ---------------------------------------------------------------------------
__global__ void __launch_bounds__(128)
attn_kernel(const float* __restrict__ q, const float* __restrict__ k,
            const float* __restrict__ v, const int* __restrict__ mask,
            float* __restrict__ y)
{
    const int bh = blockIdx.y;
    const int b = bh >> 4;
    const int h = bh & (HH - 1);
    const int q0 = blockIdx.x * 128;
    const int tid = threadIdx.x;
    const int qi = q0 + tid;

    __shared__ float ks[64 * HD];
    __shared__ float vs[64 * HD];
    __shared__ int ms[64];

    float qr[HD];
    const float* qptr = q + ((size_t)bh * TT + qi) * HD;
#pragma unroll
    for (int d = 0; d < HD; d += 4) {
        float4 t4 = *(const float4*)(qptr + d);
        qr[d] = t4.x; qr[d + 1] = t4.y; qr[d + 2] = t4.z; qr[d + 3] = t4.w;
    }

    float mrow = -INFINITY;
    float lrow = 0.f;
    float acc[HD];
#pragma unroll
    for (int d = 0; d < HD; d++) acc[d] = 0.f;

    const int jend = q0 + 127;
    for (int j0 = 0; j0 <= jend; j0 += 64) {
        const float* kbase = k + ((size_t)bh * TT + j0) * HD;
        const float* vbase = v + ((size_t)bh * TT + j0) * HD;
#pragma unroll
        for (int i = 0; i < 8; i++) {
            int fid = tid + i * 128;
            *(float4*)&ks[fid * 4] = *(const float4*)&kbase[fid * 4];
            *(float4*)&vs[fid * 4] = *(const float4*)&vbase[fid * 4];
        }
        if (tid < 64) ms[tid] = mask[b * TT + j0 + tid];
        __syncthreads();

        int jmax = qi - j0;
        if (jmax > 63) jmax = 63;
        for (int j = 0; j <= jmax; j++) {
            if (ms[j] == 0) continue;
            const float* kr = &ks[j * HD];
            float s0 = 0.f, s1 = 0.f, s2 = 0.f, s3 = 0.f;
#pragma unroll
            for (int d = 0; d < HD; d += 16) {
                float4 k0 = *(const float4*)&kr[d];
                float4 k1 = *(const float4*)&kr[d + 4];
                float4 k2 = *(const float4*)&kr[d + 8];
                float4 k3 = *(const float4*)&kr[d + 12];
                s0 += qr[d + 0] * k0.x + qr[d + 1] * k0.y + qr[d + 2] * k0.z + qr[d + 3] * k0.w;
                s1 += qr[d + 4] * k1.x + qr[d + 5] * k1.y + qr[d + 6] * k1.z + qr[d + 7] * k1.w;
                s2 += qr[d + 8] * k2.x + qr[d + 9] * k2.y + qr[d + 10] * k2.z + qr[d + 11] * k2.w;
                s3 += qr[d + 12] * k3.x + qr[d + 13] * k3.y + qr[d + 14] * k3.z + qr[d + 15] * k3.w;
            }
            float s = ((s0 + s1) + (s2 + s3)) * 0.125f;

            const float* vr = &vs[j * HD];
            if (s <= mrow) {
                float p = __expf(s - mrow);
                lrow += p;
#pragma unroll
                for (int d = 0; d < HD; d += 4) {
                    float4 v4 = *(const float4*)&vr[d];
                    acc[d + 0] += p * v4.x;
                    acc[d + 1] += p * v4.y;
                    acc[d + 2] += p * v4.z;
                    acc[d + 3] += p * v4.w;
                }
            } else {
                float c = __expf(mrow - s);
                mrow = s;
                lrow = lrow * c + 1.f;
#pragma unroll
                for (int d = 0; d < HD; d += 4) {
                    float4 v4 = *(const float4*)&vr[d];
                    acc[d + 0] = acc[d + 0] * c + v4.x;
                    acc[d + 1] = acc[d + 1] * c + v4.y;
                    acc[d + 2] = acc[d + 2] * c + v4.z;
                    acc[d + 3] = acc[d + 3] * c + v4.w;
                }
            }
        }
        __syncthreads();
    }

    float inv = 1.f / lrow;
    float* yp = y + ((size_t)(b * TT + qi)) * CC + h * HD;
#pragma unroll
    for (int d = 0; d < HD; d += 4) {
        float4 o;
        o.x = acc[d + 0] * inv;
        o.y = acc[d + 1] * inv;
        o.z = acc[d + 2] * inv;
        o.w = acc[d + 3] * inv;
        *(float4*)(yp + d) = o;
    }
}

// ---------------------------------------------------------------------------
extern "C" void kernel_launch(void* const* d_in, const int* in_sizes, int n_in,
                              void* d_out, int out_size)
{
    const float* x  = (const float*)d_in[0];
    const float* Wq = (const float*)d_in[1];
    const float* bq = (const float*)d_in[2];
    const float* Wk = (const float*)d_in[3];
    const float* bk = (const float*)d_in[4];
    const float* Wv = (const float*)d_in[5];
    const float* bv = (const float*)d_in[6];
    const float* Wp = (const float*)d_in[7];
    const float* bp = (const float*)d_in[8];
    const int* mask = (const int*)d_in[9];
    float* out = (float*)d_out;

    float *qp, *kp, *vp, *yp;
    __half *xh, *yh, *wqh, *wkh, *wvh, *wph;
    cudaGetSymbolAddress((void**)&qp,  g_q);
    cudaGetSymbolAddress((void**)&kp,  g_k);
    cudaGetSymbolAddress((void**)&vp,  g_v);
    cudaGetSymbolAddress((void**)&yp,  g_y);
    cudaGetSymbolAddress((void**)&xh,  g_xh);
    cudaGetSymbolAddress((void**)&yh,  g_yh);
    cudaGetSymbolAddress((void**)&wqh, g_wqh);
    cudaGetSymbolAddress((void**)&wkh, g_wkh);
    cudaGetSymbolAddress((void**)&wvh, g_wvh);
    cudaGetSymbolAddress((void**)&wph, g_wph);

    const int nX = MM * CC;      // 8388608
    const int nW = CC * CC;      // 1048576

    f2h_kernel<<<nX / 1024, 256>>>(x,  xh,  nX);
    f2h_kernel<<<nW / 1024, 256>>>(Wq, wqh, nW);
    f2h_kernel<<<nW / 1024, 256>>>(Wk, wkh, nW);
    f2h_kernel<<<nW / 1024, 256>>>(Wv, wvh, nW);
    f2h_kernel<<<nW / 1024, 256>>>(Wp, wph, nW);

    dim3 gg(CC / 128, MM / 128);   // (8, 64)
    gemm_mma<1><<<gg, 256>>>(xh, wqh, bq, qp, MM, CC, CC);
    gemm_mma<1><<<gg, 256>>>(xh, wkh, bk, kp, MM, CC, CC);
    gemm_mma<1><<<gg, 256>>>(xh, wvh, bv, vp, MM, CC, CC);

    attn_kernel<<<dim3(TT / 128, BB * HH), 128>>>(qp, kp, vp, mask, yp);

    f2h_kernel<<<nX / 1024, 256>>>(yp, yh, nX);
    gemm_mma<0><<<gg, 256>>>(yh, wph, bp, out, MM, CC, CC);
}

// round 16
// speedup vs baseline: 6.6728x; 4.1102x over previous
#include <cuda_runtime.h>
#include <cuda_fp16.h>
#include <math.h>
#include <cstdint>

// Problem constants
#define BB 4
#define TT 2048
#define CC 1024
#define HH 16
#define HD 64
#define MM (BB * TT)   // 8192

#define NEG -1e30f     // finite "minus infinity": exp(NEG - m) == 0, NEG-NEG == 0

// ---------------- scratch (device globals; no allocs allowed) ----------------
__device__ __half g_qh[(size_t)MM * CC];   // [B,H,T,HD] fp16
__device__ __half g_kh[(size_t)MM * CC];
__device__ __half g_vh[(size_t)MM * CC];
__device__ __half g_yh[(size_t)MM * CC];   // [B,T,C] fp16
__device__ __half g_xh[(size_t)MM * CC];
__device__ __half g_wqh[(size_t)CC * CC];
__device__ __half g_wkh[(size_t)CC * CC];
__device__ __half g_wvh[(size_t)CC * CC];
__device__ __half g_wph[(size_t)CC * CC];

__device__ __forceinline__ uint32_t smem_to_u32(const void* p) {
    uint32_t a;
    asm("{ .reg .u64 t; cvta.to.shared.u64 t, %1; cvt.u32.u64 %0, t; }"
        : "=r"(a) : "l"(p));
    return a;
}

__device__ __forceinline__ void ldsm_x4(uint32_t addr, uint32_t& r0, uint32_t& r1,
                                        uint32_t& r2, uint32_t& r3) {
    asm volatile("ldmatrix.sync.aligned.m8n8.x4.shared.b16 {%0,%1,%2,%3}, [%4];"
                 : "=r"(r0), "=r"(r1), "=r"(r2), "=r"(r3) : "r"(addr));
}

__device__ __forceinline__ void ldsm_x4_t(uint32_t addr, uint32_t& r0, uint32_t& r1,
                                          uint32_t& r2, uint32_t& r3) {
    asm volatile("ldmatrix.sync.aligned.m8n8.x4.trans.shared.b16 {%0,%1,%2,%3}, [%4];"
                 : "=r"(r0), "=r"(r1), "=r"(r2), "=r"(r3) : "r"(addr));
}

__device__ __forceinline__ void mma16816(float* c, uint32_t a0, uint32_t a1,
                                         uint32_t a2, uint32_t a3,
                                         uint32_t b0, uint32_t b1) {
    asm volatile(
        "mma.sync.aligned.m16n8k16.row.col.f32.f16.f16.f32 "
        "{%0,%1,%2,%3}, {%4,%5,%6,%7}, {%8,%9}, {%0,%1,%2,%3};"
        : "+f"(c[0]), "+f"(c[1]), "+f"(c[2]), "+f"(c[3])
        : "r"(a0), "r"(a1), "r"(a2), "r"(a3), "r"(b0), "r"(b1));
}

__device__ __forceinline__ uint32_t packh2(float a, float b) {
    __half2 h = __floats2half2_rn(a, b);
    return *reinterpret_cast<uint32_t*>(&h);
}

// ---------------- fp32 -> fp16 conversion ----------------
__global__ void __launch_bounds__(256)
f2h_kernel(const float* __restrict__ in, __half* __restrict__ out, int n)
{
    int i = (blockIdx.x * 256 + threadIdx.x) * 4;
    if (i < n) {
        float4 v = *(const float4*)(in + i);
        reinterpret_cast<__half2*>(out + i)[0] = __floats2half2_rn(v.x, v.y);
        reinterpret_cast<__half2*>(out + i)[1] = __floats2half2_rn(v.z, v.w);
    }
}

// ---------------------------------------------------------------------------
// mma.sync fp16 GEMM: out = A[M,K] @ W[N,K]^T + bias   (R8-proven core)
// MODE 0: fp32 out row-major [M,N].  MODE 1: fp16 out scattered to [B,H,T,HD].
// ---------------------------------------------------------------------------
#define RS 40
#define BUFB (128 * RS * 2)

template <int MODE>
__global__ void __launch_bounds__(256)
gemm_mma(const __half* __restrict__ A, const __half* __restrict__ W,
         const float* __restrict__ bias, void* __restrict__ out_v,
         int M, int N, int K)
{
    __shared__ __half As[2][128 * RS];
    __shared__ __half Bs[2][128 * RS];

    const int tid = threadIdx.x;
    const int lid = tid & 31;
    const int wid = tid >> 5;
    const int bm = blockIdx.y * 128;
    const int bn = blockIdx.x * 128;
    const int wm = (wid >> 2) * 64;
    const int wn = (wid & 3) * 32;

    const uint32_t as_base = smem_to_u32(As);
    const uint32_t bs_base = smem_to_u32(Bs);

    float acc[4][4][4];
#pragma unroll
    for (int f = 0; f < 4; f++)
#pragma unroll
        for (int g = 0; g < 4; g++)
#pragma unroll
            for (int e = 0; e < 4; e++) acc[f][g][e] = 0.f;

    const int r0 = tid >> 2;
    const int c8 = (tid & 3) * 8;
    const uint32_t soff0 = (uint32_t)(r0 * RS + c8) * 2;
    const uint32_t soff1 = (uint32_t)((r0 + 64) * RS + c8) * 2;

    uint32_t a_off[4], b_off[2];
#pragma unroll
    for (int f = 0; f < 4; f++) {
        int row = wm + f * 16 + (lid & 15);
        int ko  = ((lid >> 4) & 1) * 8;
        a_off[f] = (uint32_t)(row * RS + ko) * 2;
    }
#pragma unroll
    for (int p = 0; p < 2; p++) {
        int nrow = wn + p * 16 + ((lid >> 4) & 1) * 8 + (lid & 7);
        int ko   = ((lid >> 3) & 1) * 8;
        b_off[p] = (uint32_t)(nrow * RS + ko) * 2;
    }

    const int NS = K / 32;

    {
        const __half* ag = A + (size_t)(bm + r0) * K + c8;
        const __half* wg = W + (size_t)(bn + r0) * K + c8;
        *(float4*)((char*)As[0] + soff0) = *(const float4*)ag;
        *(float4*)((char*)As[0] + soff1) = *(const float4*)(ag + (size_t)64 * K);
        *(float4*)((char*)Bs[0] + soff0) = *(const float4*)wg;
        *(float4*)((char*)Bs[0] + soff1) = *(const float4*)(wg + (size_t)64 * K);
    }
    __syncthreads();

#pragma unroll 1
    for (int s = 0; s < NS; s++) {
        const int buf = s & 1;
        float4 pa0, pa1, pb0, pb1;
        if (s + 1 < NS) {
            const int k0 = (s + 1) * 32;
            const __half* ag = A + (size_t)(bm + r0) * K + k0 + c8;
            const __half* wg = W + (size_t)(bn + r0) * K + k0 + c8;
            pa0 = *(const float4*)ag;
            pa1 = *(const float4*)(ag + (size_t)64 * K);
            pb0 = *(const float4*)wg;
            pb1 = *(const float4*)(wg + (size_t)64 * K);
        }

        const uint32_t ab = as_base + buf * BUFB;
        const uint32_t bb = bs_base + buf * BUFB;
#pragma unroll
        for (int kk = 0; kk < 2; kk++) {
            uint32_t a[4][4];
#pragma unroll
            for (int f = 0; f < 4; f++)
                ldsm_x4(ab + a_off[f] + kk * 32, a[f][0], a[f][1], a[f][2], a[f][3]);
            uint32_t b[2][4];
#pragma unroll
            for (int p = 0; p < 2; p++)
                ldsm_x4(bb + b_off[p] + kk * 32, b[p][0], b[p][1], b[p][2], b[p][3]);
#pragma unroll
            for (int f = 0; f < 4; f++)
#pragma unroll
                for (int g = 0; g < 4; g++)
                    mma16816(acc[f][g], a[f][0], a[f][1], a[f][2], a[f][3],
                             b[g >> 1][(g & 1) * 2], b[g >> 1][(g & 1) * 2 + 1]);
        }

        if (s + 1 < NS) {
            __syncthreads();
            const int nb = (s + 1) & 1;
            *(float4*)((char*)As[nb] + soff0) = pa0;
            *(float4*)((char*)As[nb] + soff1) = pa1;
            *(float4*)((char*)Bs[nb] + soff0) = pb0;
            *(float4*)((char*)Bs[nb] + soff1) = pb1;
            __syncthreads();
        }
    }

#pragma unroll
    for (int f = 0; f < 4; f++) {
#pragma unroll
        for (int g = 0; g < 4; g++) {
            int m0 = bm + wm + f * 16 + (lid >> 2);
            int n0 = bn + wn + g * 8 + (lid & 3) * 2;
            float lo0 = acc[f][g][0] + bias[n0];
            float lo1 = acc[f][g][1] + bias[n0 + 1];
            float hi0 = acc[f][g][2] + bias[n0];
            float hi1 = acc[f][g][3] + bias[n0 + 1];
            if (MODE == 0) {
                float* out = (float*)out_v;
                *(float2*)&out[(size_t)m0 * N + n0] = make_float2(lo0, lo1);
                *(float2*)&out[(size_t)(m0 + 8) * N + n0] = make_float2(hi0, hi1);
            } else {
                __half* out = (__half*)out_v;
                int b = m0 >> 11;
                int t = m0 & (TT - 1);
                int h = n0 >> 6;
                int d = n0 & (HD - 1);
                size_t base = ((size_t)(b * HH + h) * TT + t) * HD + d;
                *(__half2*)&out[base] = __floats2half2_rn(lo0, lo1);
                *(__half2*)&out[base + (size_t)8 * HD] = __floats2half2_rn(hi0, hi1);
            }
        }
    }
}

// ---------------------------------------------------------------------------
// Tensor-core flash attention (causal + padding mask), INF-free math,
// FIXED smem tile loads (float4 = 8 halfs!).
// q/k/v fp16 [B,H,T,HD]; y fp16 [B,T,C]. fp32 softmax + fp32 O accumulation.
// CTA: 128 q rows x one (b,h). 4 warps, 32 q rows each. KV tiles of 64.
// ---------------------------------------------------------------------------
__global__ void __launch_bounds__(128)
attn_mma(const __half* __restrict__ q, const __half* __restrict__ k,
         const __half* __restrict__ v, const int* __restrict__ mask,
         __half* __restrict__ y)
{
    const int bh = blockIdx.y;
    const int b = bh >> 4;
    const int h = bh & (HH - 1);
    const int q0 = blockIdx.x * 128;
    const int tid = threadIdx.x;
    const int lid = tid & 31;
    const int wid = tid >> 5;
    const int wm = wid * 32;

    __shared__ __half Qs[128][72];
    __shared__ __half Ks[64][72];
    __shared__ __half Vs[64][72];
    __shared__ float msk[64];

    // ---- load Q tile: 128 rows x 64 halfs = 1024 float4 (8 per thread) ----
    {
        const __half* qg = q + ((size_t)bh * TT + q0) * HD;
#pragma unroll
        for (int i = 0; i < 8; i++) {
            int idx = tid + i * 128;           // 0..1023
            int row = idx >> 3;
            int c8  = (idx & 7) * 8;           // float4 = 8 halfs
            *(float4*)&Qs[row][c8] = *(const float4*)(qg + (size_t)row * HD + c8);
        }
    }
    __syncthreads();

    // Q A-fragments: [f(m16)][kc(k16)][4]
    uint32_t qf[2][4][4];
    {
        const uint32_t qs_base = smem_to_u32(Qs);
#pragma unroll
        for (int f = 0; f < 2; f++)
#pragma unroll
            for (int kc = 0; kc < 4; kc++) {
                uint32_t addr = qs_base +
                    ((uint32_t)((wm + f * 16 + (lid & 15)) * 72 +
                                kc * 16 + ((lid >> 4) & 1) * 8)) * 2;
                ldsm_x4(addr, qf[f][kc][0], qf[f][kc][1], qf[f][kc][2], qf[f][kc][3]);
            }
    }

    float o[2][8][4];
#pragma unroll
    for (int f = 0; f < 2; f++)
#pragma unroll
        for (int g = 0; g < 8; g++)
#pragma unroll
            for (int e = 0; e < 4; e++) o[f][g][e] = 0.f;
    float mrow[2][2] = {{NEG, NEG}, {NEG, NEG}};
    float lrow[2][2] = {{0.f, 0.f}, {0.f, 0.f}};

    const uint32_t ks_base = smem_to_u32(Ks);
    const uint32_t vs_base = smem_to_u32(Vs);
    const int ntile = (q0 + 128) / 64;

    for (int jt = 0; jt < ntile; jt++) {
        const int j0 = jt * 64;
        // ---- load K, V tiles: 64 rows x 64 halfs = 512 float4 each ----
        {
            const __half* kg = k + ((size_t)bh * TT + j0) * HD;
            const __half* vg = v + ((size_t)bh * TT + j0) * HD;
#pragma unroll
            for (int i = 0; i < 4; i++) {
                int idx = tid + i * 128;       // 0..511
                int row = idx >> 3;
                int c8  = (idx & 7) * 8;       // float4 = 8 halfs
                *(float4*)&Ks[row][c8] = *(const float4*)(kg + (size_t)row * HD + c8);
                *(float4*)&Vs[row][c8] = *(const float4*)(vg + (size_t)row * HD + c8);
            }
            if (tid < 64) msk[tid] = mask[b * TT + j0 + tid] ? 0.f : NEG;
        }
        __syncthreads();

        if (j0 <= q0 + wm + 31) {   // tile not fully causal-masked for this warp
            // ---- S = Q @ K^T ----
            float s[2][8][4];
#pragma unroll
            for (int f = 0; f < 2; f++)
#pragma unroll
                for (int g = 0; g < 8; g++)
#pragma unroll
                    for (int e = 0; e < 4; e++) s[f][g][e] = 0.f;

#pragma unroll
            for (int kc = 0; kc < 4; kc++) {
#pragma unroll
                for (int gp = 0; gp < 4; gp++) {
                    uint32_t r0, r1, r2, r3;
                    uint32_t addr = ks_base +
                        ((uint32_t)((gp * 16 + ((lid >> 4) & 1) * 8 + (lid & 7)) * 72 +
                                    kc * 16 + ((lid >> 3) & 1) * 8)) * 2;
                    ldsm_x4(addr, r0, r1, r2, r3);
#pragma unroll
                    for (int f = 0; f < 2; f++) {
                        mma16816(s[f][2 * gp], qf[f][kc][0], qf[f][kc][1],
                                 qf[f][kc][2], qf[f][kc][3], r0, r1);
                        mma16816(s[f][2 * gp + 1], qf[f][kc][0], qf[f][kc][1],
                                 qf[f][kc][2], qf[f][kc][3], r2, r3);
                    }
                }
            }

            // ---- scale + masks + online softmax (all finite) ----
            const bool needc = (j0 + 63) > (q0 + wm);
            float corr[2][2];
            uint32_t ph[2][8][2];
#pragma unroll
            for (int f = 0; f < 2; f++) {
                const int rlo = q0 + wm + f * 16 + (lid >> 2);
                const int rhi = rlo + 8;
#pragma unroll
                for (int g = 0; g < 8; g++) {
                    int cb = g * 8 + (lid & 3) * 2;
                    float m0a = msk[cb], m1a = msk[cb + 1];
                    float v0 = s[f][g][0] * 0.125f + m0a;
                    float v1 = s[f][g][1] * 0.125f + m1a;
                    float v2 = s[f][g][2] * 0.125f + m0a;
                    float v3 = s[f][g][3] * 0.125f + m1a;
                    if (needc) {
                        if (j0 + cb     > rlo) v0 = NEG;
                        if (j0 + cb + 1 > rlo) v1 = NEG;
                        if (j0 + cb     > rhi) v2 = NEG;
                        if (j0 + cb + 1 > rhi) v3 = NEG;
                    }
                    s[f][g][0] = v0; s[f][g][1] = v1; s[f][g][2] = v2; s[f][g][3] = v3;
                }
#pragma unroll
                for (int sub = 0; sub < 2; sub++) {
                    float mx = NEG;
#pragma unroll
                    for (int g = 0; g < 8; g++)
                        mx = fmaxf(mx, fmaxf(s[f][g][2 * sub], s[f][g][2 * sub + 1]));
                    mx = fmaxf(mx, __shfl_xor_sync(0xffffffffu, mx, 1));
                    mx = fmaxf(mx, __shfl_xor_sync(0xffffffffu, mx, 2));
                    float mnew = fmaxf(mrow[f][sub], mx);
                    float c = __expf(mrow[f][sub] - mnew);   // finite - finite
                    corr[f][sub] = c;
                    mrow[f][sub] = mnew;
                    lrow[f][sub] *= c;
                }
#pragma unroll
                for (int g = 0; g < 8; g++) {
                    float p0 = __expf(s[f][g][0] - mrow[f][0]);
                    float p1 = __expf(s[f][g][1] - mrow[f][0]);
                    float p2 = __expf(s[f][g][2] - mrow[f][1]);
                    float p3 = __expf(s[f][g][3] - mrow[f][1]);
                    lrow[f][0] += p0 + p1;
                    lrow[f][1] += p2 + p3;
                    ph[f][g][0] = packh2(p0, p1);
                    ph[f][g][1] = packh2(p2, p3);
                }
#pragma unroll
                for (int g = 0; g < 8; g++) {
                    o[f][g][0] *= corr[f][0];
                    o[f][g][1] *= corr[f][0];
                    o[f][g][2] *= corr[f][1];
                    o[f][g][3] *= corr[f][1];
                }
            }

            // ---- O += P @ V ----
#pragma unroll
            for (int kc = 0; kc < 4; kc++) {
#pragma unroll
                for (int gd = 0; gd < 4; gd++) {
                    uint32_t r0, r1, r2, r3;
                    uint32_t addr = vs_base +
                        ((uint32_t)((kc * 16 + ((lid >> 3) & 1) * 8 + (lid & 7)) * 72 +
                                    gd * 16 + ((lid >> 4) & 1) * 8)) * 2;
                    ldsm_x4_t(addr, r0, r1, r2, r3);
#pragma unroll
                    for (int f = 0; f < 2; f++) {
                        mma16816(o[f][2 * gd], ph[f][2 * kc][0], ph[f][2 * kc][1],
                                 ph[f][2 * kc + 1][0], ph[f][2 * kc + 1][1], r0, r1);
                        mma16816(o[f][2 * gd + 1], ph[f][2 * kc][0], ph[f][2 * kc][1],
                                 ph[f][2 * kc + 1][0], ph[f][2 * kc + 1][1], r2, r3);
                    }
                }
            }
        }
        __syncthreads();
    }

    // ---- finalize + store y (fp16, [B,T,C]) ----
    float inv[2][2];
#pragma unroll
    for (int f = 0; f < 2; f++)
#pragma unroll
        for (int sub = 0; sub < 2; sub++) {
            float lf = lrow[f][sub];
            lf += __shfl_xor_sync(0xffffffffu, lf, 1);
            lf += __shfl_xor_sync(0xffffffffu, lf, 2);
            inv[f][sub] = 1.f / fmaxf(lf, 1e-20f);
        }

#pragma unroll
    for (int f = 0; f < 2; f++) {
        int row = q0 + wm + f * 16 + (lid >> 2);
#pragma unroll
        for (int g = 0; g < 8; g++) {
            __half* yp = y + ((size_t)(b * TT + row)) * CC + h * HD + g * 8 + (lid & 3) * 2;
            *(__half2*)yp = __floats2half2_rn(o[f][g][0] * inv[f][0],
                                              o[f][g][1] * inv[f][0]);
            *(__half2*)(yp + (size_t)8 * CC) = __floats2half2_rn(o[f][g][2] * inv[f][1],
                                                                 o[f][g][3] * inv[f][1]);
        }
    }
}

// ---------------------------------------------------------------------------
extern "C" void kernel_launch(void* const* d_in, const int* in_sizes, int n_in,
                              void* d_out, int out_size)
{
    const float* x  = (const float*)d_in[0];
    const float* Wq = (const float*)d_in[1];
    const float* bq = (const float*)d_in[2];
    const float* Wk = (const float*)d_in[3];
    const float* bk = (const float*)d_in[4];
    const float* Wv = (const float*)d_in[5];
    const float* bv = (const float*)d_in[6];
    const float* Wp = (const float*)d_in[7];
    const float* bp = (const float*)d_in[8];
    const int* mask = (const int*)d_in[9];
    float* out = (float*)d_out;

    __half *qh, *kh, *vh, *yh, *xh, *wqh, *wkh, *wvh, *wph;
    cudaGetSymbolAddress((void**)&qh,  g_qh);
    cudaGetSymbolAddress((void**)&kh,  g_kh);
    cudaGetSymbolAddress((void**)&vh,  g_vh);
    cudaGetSymbolAddress((void**)&yh,  g_yh);
    cudaGetSymbolAddress((void**)&xh,  g_xh);
    cudaGetSymbolAddress((void**)&wqh, g_wqh);
    cudaGetSymbolAddress((void**)&wkh, g_wkh);
    cudaGetSymbolAddress((void**)&wvh, g_wvh);
    cudaGetSymbolAddress((void**)&wph, g_wph);

    const int nX = MM * CC;      // 8388608
    const int nW = CC * CC;      // 1048576

    f2h_kernel<<<nX / 1024, 256>>>(x,  xh,  nX);
    f2h_kernel<<<nW / 1024, 256>>>(Wq, wqh, nW);
    f2h_kernel<<<nW / 1024, 256>>>(Wk, wkh, nW);
    f2h_kernel<<<nW / 1024, 256>>>(Wv, wvh, nW);
    f2h_kernel<<<nW / 1024, 256>>>(Wp, wph, nW);

    dim3 gg(CC / 128, MM / 128);   // (8, 64)
    gemm_mma<1><<<gg, 256>>>(xh, wqh, bq, qh, MM, CC, CC);
    gemm_mma<1><<<gg, 256>>>(xh, wkh, bk, kh, MM, CC, CC);
    gemm_mma<1><<<gg, 256>>>(xh, wvh, bv, vh, MM, CC, CC);

    attn_mma<<<dim3(TT / 128, BB * HH), 128>>>(qh, kh, vh, mask, yh);

    gemm_mma<0><<<gg, 256>>>(yh, wph, bp, out, MM, CC, CC);
}

// round 17
// speedup vs baseline: 6.9979x; 1.0487x over previous
#include <cuda_runtime.h>
#include <cuda_fp16.h>
#include <math.h>
#include <cstdint>

// Problem constants
#define BB 4
#define TT 2048
#define CC 1024
#define HH 16
#define HD 64
#define MM (BB * TT)   // 8192

#define NEG -1e30f     // finite "minus infinity"

// ---------------- scratch (device globals; no allocs allowed) ----------------
__device__ __half g_qh[(size_t)MM * CC];   // [B,H,T,HD] fp16
__device__ __half g_kh[(size_t)MM * CC];
__device__ __half g_vh[(size_t)MM * CC];
__device__ __half g_yh[(size_t)MM * CC];   // [B,T,C] fp16
__device__ __half g_xh[(size_t)MM * CC];
__device__ __half g_wqh[(size_t)CC * CC];
__device__ __half g_wkh[(size_t)CC * CC];
__device__ __half g_wvh[(size_t)CC * CC];
__device__ __half g_wph[(size_t)CC * CC];

__device__ __forceinline__ uint32_t smem_to_u32(const void* p) {
    uint32_t a;
    asm("{ .reg .u64 t; cvta.to.shared.u64 t, %1; cvt.u32.u64 %0, t; }"
        : "=r"(a) : "l"(p));
    return a;
}

__device__ __forceinline__ void ldsm_x4(uint32_t addr, uint32_t& r0, uint32_t& r1,
                                        uint32_t& r2, uint32_t& r3) {
    asm volatile("ldmatrix.sync.aligned.m8n8.x4.shared.b16 {%0,%1,%2,%3}, [%4];"
                 : "=r"(r0), "=r"(r1), "=r"(r2), "=r"(r3) : "r"(addr));
}

__device__ __forceinline__ void ldsm_x4_t(uint32_t addr, uint32_t& r0, uint32_t& r1,
                                          uint32_t& r2, uint32_t& r3) {
    asm volatile("ldmatrix.sync.aligned.m8n8.x4.trans.shared.b16 {%0,%1,%2,%3}, [%4];"
                 : "=r"(r0), "=r"(r1), "=r"(r2), "=r"(r3) : "r"(addr));
}

__device__ __forceinline__ void mma16816(float* c, uint32_t a0, uint32_t a1,
                                         uint32_t a2, uint32_t a3,
                                         uint32_t b0, uint32_t b1) {
    asm volatile(
        "mma.sync.aligned.m16n8k16.row.col.f32.f16.f16.f32 "
        "{%0,%1,%2,%3}, {%4,%5,%6,%7}, {%8,%9}, {%0,%1,%2,%3};"
        : "+f"(c[0]), "+f"(c[1]), "+f"(c[2]), "+f"(c[3])
        : "r"(a0), "r"(a1), "r"(a2), "r"(a3), "r"(b0), "r"(b1));
}

__device__ __forceinline__ uint32_t packh2(float a, float b) {
    __half2 h = __floats2half2_rn(a, b);
    return *reinterpret_cast<uint32_t*>(&h);
}

__device__ __forceinline__ void cp16(uint32_t saddr, const void* gaddr) {
    asm volatile("cp.async.cg.shared.global [%0], [%1], 16;"
                 :: "r"(saddr), "l"(gaddr));
}
#define CP_COMMIT() asm volatile("cp.async.commit_group;" ::: "memory")
#define CP_WAIT1()  asm volatile("cp.async.wait_group 1;" ::: "memory")

// ---------------- fp32 -> fp16 conversion ----------------
__global__ void __launch_bounds__(256)
f2h_kernel(const float* __restrict__ in, __half* __restrict__ out, int n)
{
    int i = (blockIdx.x * 256 + threadIdx.x) * 4;
    if (i < n) {
        float4 v = *(const float4*)(in + i);
        reinterpret_cast<__half2*>(out + i)[0] = __floats2half2_rn(v.x, v.y);
        reinterpret_cast<__half2*>(out + i)[1] = __floats2half2_rn(v.z, v.w);
    }
}

// ---------------------------------------------------------------------------
// cp.async 3-stage pipelined fp16 GEMM: out = A[M,K] @ W[N,K]^T + bias
// MODE 0: fp32 out row-major [M,N].  MODE 1: fp16 out scattered to [B,H,T,HD].
// blockIdx.z selects among (W0,b0,o0)/(W1,b1,o1)/(W2,b2,o2)  (QKV fusion).
// CTA tile 128x128, 8 warps (2m x 4n), warp tile 64x32, K staged by 32.
// ---------------------------------------------------------------------------
#define RS 40                            // smem row stride in halfs
#define BUFB (128 * RS * 2)              // bytes per (tile, stage) = 10240
#define GEMM_SMEM (6 * BUFB)             // 3 stages x (A + B) = 61440

template <int MODE>
__global__ void __launch_bounds__(256)
gemm_cp(const __half* __restrict__ A,
        const __half* __restrict__ W0, const __half* __restrict__ W1,
        const __half* __restrict__ W2,
        const float* __restrict__ b0, const float* __restrict__ b1,
        const float* __restrict__ b2,
        void* __restrict__ o0, void* __restrict__ o1, void* __restrict__ o2,
        int K)
{
    extern __shared__ char gsm[];
    const uint32_t as_base = smem_to_u32(gsm);
    const uint32_t bs_base = as_base + 3 * BUFB;

    const int z = blockIdx.z;
    const __half* W = (z == 0) ? W0 : (z == 1) ? W1 : W2;
    const float* bias = (z == 0) ? b0 : (z == 1) ? b1 : b2;
    void* out_v = (z == 0) ? o0 : (z == 1) ? o1 : o2;

    const int tid = threadIdx.x;
    const int lid = tid & 31;
    const int wid = tid >> 5;
    const int bm = blockIdx.y * 128;
    const int bn = blockIdx.x * 128;
    const int wm = (wid >> 2) * 64;
    const int wn = (wid & 3) * 32;

    float acc[4][4][4];
#pragma unroll
    for (int f = 0; f < 4; f++)
#pragma unroll
        for (int g = 0; g < 4; g++)
#pragma unroll
            for (int e = 0; e < 4; e++) acc[f][g][e] = 0.f;

    // gmem<->smem mapping: thread loads 16B at (r0, c8) and (r0+64, c8)
    const int r0 = tid >> 2;
    const int c8 = (tid & 3) * 8;
    const uint32_t soff0 = (uint32_t)(r0 * RS + c8) * 2;
    const uint32_t soff1 = (uint32_t)((r0 + 64) * RS + c8) * 2;
    const __half* ag = A + (size_t)(bm + r0) * K + c8;
    const __half* wg = W + (size_t)(bn + r0) * K + c8;
    const size_t rstep = (size_t)64 * K;

    // ldmatrix per-thread byte offsets (within a stage buffer)
    uint32_t a_off[4], b_off[2];
#pragma unroll
    for (int f = 0; f < 4; f++) {
        int row = wm + f * 16 + (lid & 15);
        int ko  = ((lid >> 4) & 1) * 8;
        a_off[f] = (uint32_t)(row * RS + ko) * 2;
    }
#pragma unroll
    for (int p = 0; p < 2; p++) {
        int nrow = wn + p * 16 + ((lid >> 4) & 1) * 8 + (lid & 7);
        int ko   = ((lid >> 3) & 1) * 8;
        b_off[p] = (uint32_t)(nrow * RS + ko) * 2;
    }

    const int NS = K / 32;

    // prologue: stages 0, 1
#pragma unroll
    for (int s = 0; s < 2; s++) {
        const int k0 = s * 32;
        cp16(as_base + s * BUFB + soff0, ag + k0);
        cp16(as_base + s * BUFB + soff1, ag + rstep + k0);
        cp16(bs_base + s * BUFB + soff0, wg + k0);
        cp16(bs_base + s * BUFB + soff1, wg + rstep + k0);
        CP_COMMIT();
    }

#pragma unroll 1
    for (int s = 0; s < NS; s++) {
        CP_WAIT1();          // stage s complete (only stage s+1 may be pending)
        __syncthreads();

        // issue loads for stage s+2 (buffer (s+2)%3, consumed at stage s-1)
        if (s + 2 < NS) {
            const int ls = (s + 2) % 3;
            const int k0 = (s + 2) * 32;
            cp16(as_base + ls * BUFB + soff0, ag + k0);
            cp16(as_base + ls * BUFB + soff1, ag + rstep + k0);
            cp16(bs_base + ls * BUFB + soff0, wg + k0);
            cp16(bs_base + ls * BUFB + soff1, wg + rstep + k0);
        }
        CP_COMMIT();         // always commit (empty groups keep the count uniform)

        const uint32_t ab = as_base + (s % 3) * BUFB;
        const uint32_t bb = bs_base + (s % 3) * BUFB;
#pragma unroll
        for (int kk = 0; kk < 2; kk++) {
            uint32_t a[4][4];
#pragma unroll
            for (int f = 0; f < 4; f++)
                ldsm_x4(ab + a_off[f] + kk * 32, a[f][0], a[f][1], a[f][2], a[f][3]);
            uint32_t b[2][4];
#pragma unroll
            for (int p = 0; p < 2; p++)
                ldsm_x4(bb + b_off[p] + kk * 32, b[p][0], b[p][1], b[p][2], b[p][3]);
#pragma unroll
            for (int f = 0; f < 4; f++)
#pragma unroll
                for (int g = 0; g < 4; g++)
                    mma16816(acc[f][g], a[f][0], a[f][1], a[f][2], a[f][3],
                             b[g >> 1][(g & 1) * 2], b[g >> 1][(g & 1) * 2 + 1]);
        }
    }

    // epilogue
#pragma unroll
    for (int f = 0; f < 4; f++) {
#pragma unroll
        for (int g = 0; g < 4; g++) {
            int m0 = bm + wm + f * 16 + (lid >> 2);
            int n0 = bn + wn + g * 8 + (lid & 3) * 2;
            float lo0 = acc[f][g][0] + bias[n0];
            float lo1 = acc[f][g][1] + bias[n0 + 1];
            float hi0 = acc[f][g][2] + bias[n0];
            float hi1 = acc[f][g][3] + bias[n0 + 1];
            if (MODE == 0) {
                float* out = (float*)out_v;
                *(float2*)&out[(size_t)m0 * CC + n0] = make_float2(lo0, lo1);
                *(float2*)&out[(size_t)(m0 + 8) * CC + n0] = make_float2(hi0, hi1);
            } else {
                __half* out = (__half*)out_v;
                int b = m0 >> 11;
                int t = m0 & (TT - 1);
                int h = n0 >> 6;
                int d = n0 & (HD - 1);
                size_t base = ((size_t)(b * HH + h) * TT + t) * HD + d;
                *(__half2*)&out[base] = __floats2half2_rn(lo0, lo1);
                *(__half2*)&out[base + (size_t)8 * HD] = __floats2half2_rn(hi0, hi1);
            }
        }
    }
}

// ---------------------------------------------------------------------------
// Tensor-core flash attention (R16-proven, unchanged).
// q/k/v fp16 [B,H,T,HD]; y fp16 [B,T,C]. fp32 softmax + fp32 O accumulation.
// CTA: 128 q rows x one (b,h). 4 warps, 32 q rows each. KV tiles of 64.
// ---------------------------------------------------------------------------
__global__ void __launch_bounds__(128)
attn_mma(const __half* __restrict__ q, const __half* __restrict__ k,
         const __half* __restrict__ v, const int* __restrict__ mask,
         __half* __restrict__ y)
{
    const int bh = blockIdx.y;
    const int b = bh >> 4;
    const int h = bh & (HH - 1);
    const int q0 = blockIdx.x * 128;
    const int tid = threadIdx.x;
    const int lid = tid & 31;
    const int wid = tid >> 5;
    const int wm = wid * 32;

    __shared__ __half Qs[128][72];
    __shared__ __half Ks[64][72];
    __shared__ __half Vs[64][72];
    __shared__ float msk[64];

    {
        const __half* qg = q + ((size_t)bh * TT + q0) * HD;
#pragma unroll
        for (int i = 0; i < 8; i++) {
            int idx = tid + i * 128;
            int row = idx >> 3;
            int c8  = (idx & 7) * 8;
            *(float4*)&Qs[row][c8] = *(const float4*)(qg + (size_t)row * HD + c8);
        }
    }
    __syncthreads();

    uint32_t qf[2][4][4];
    {
        const uint32_t qs_base = smem_to_u32(Qs);
#pragma unroll
        for (int f = 0; f < 2; f++)
#pragma unroll
            for (int kc = 0; kc < 4; kc++) {
                uint32_t addr = qs_base +
                    ((uint32_t)((wm + f * 16 + (lid & 15)) * 72 +
                                kc * 16 + ((lid >> 4) & 1) * 8)) * 2;
                ldsm_x4(addr, qf[f][kc][0], qf[f][kc][1], qf[f][kc][2], qf[f][kc][3]);
            }
    }

    float o[2][8][4];
#pragma unroll
    for (int f = 0; f < 2; f++)
#pragma unroll
        for (int g = 0; g < 8; g++)
#pragma unroll
            for (int e = 0; e < 4; e++) o[f][g][e] = 0.f;
    float mrow[2][2] = {{NEG, NEG}, {NEG, NEG}};
    float lrow[2][2] = {{0.f, 0.f}, {0.f, 0.f}};

    const uint32_t ks_base = smem_to_u32(Ks);
    const uint32_t vs_base = smem_to_u32(Vs);
    const int ntile = (q0 + 128) / 64;

    for (int jt = 0; jt < ntile; jt++) {
        const int j0 = jt * 64;
        {
            const __half* kg = k + ((size_t)bh * TT + j0) * HD;
            const __half* vg = v + ((size_t)bh * TT + j0) * HD;
#pragma unroll
            for (int i = 0; i < 4; i++) {
                int idx = tid + i * 128;
                int row = idx >> 3;
                int c8  = (idx & 7) * 8;
                *(float4*)&Ks[row][c8] = *(const float4*)(kg + (size_t)row * HD + c8);
                *(float4*)&Vs[row][c8] = *(const float4*)(vg + (size_t)row * HD + c8);
            }
            if (tid < 64) msk[tid] = mask[b * TT + j0 + tid] ? 0.f : NEG;
        }
        __syncthreads();

        if (j0 <= q0 + wm + 31) {
            float s[2][8][4];
#pragma unroll
            for (int f = 0; f < 2; f++)
#pragma unroll
                for (int g = 0; g < 8; g++)
#pragma unroll
                    for (int e = 0; e < 4; e++) s[f][g][e] = 0.f;

#pragma unroll
            for (int kc = 0; kc < 4; kc++) {
#pragma unroll
                for (int gp = 0; gp < 4; gp++) {
                    uint32_t r0, r1, r2, r3;
                    uint32_t addr = ks_base +
                        ((uint32_t)((gp * 16 + ((lid >> 4) & 1) * 8 + (lid & 7)) * 72 +
                                    kc * 16 + ((lid >> 3) & 1) * 8)) * 2;
                    ldsm_x4(addr, r0, r1, r2, r3);
#pragma unroll
                    for (int f = 0; f < 2; f++) {
                        mma16816(s[f][2 * gp], qf[f][kc][0], qf[f][kc][1],
                                 qf[f][kc][2], qf[f][kc][3], r0, r1);
                        mma16816(s[f][2 * gp + 1], qf[f][kc][0], qf[f][kc][1],
                                 qf[f][kc][2], qf[f][kc][3], r2, r3);
                    }
                }
            }

            const bool needc = (j0 + 63) > (q0 + wm);
            float corr[2][2];
            uint32_t ph[2][8][2];
#pragma unroll
            for (int f = 0; f < 2; f++) {
                const int rlo = q0 + wm + f * 16 + (lid >> 2);
                const int rhi = rlo + 8;
#pragma unroll
                for (int g = 0; g < 8; g++) {
                    int cb = g * 8 + (lid & 3) * 2;
                    float m0a = msk[cb], m1a = msk[cb + 1];
                    float v0 = s[f][g][0] * 0.125f + m0a;
                    float v1 = s[f][g][1] * 0.125f + m1a;
                    float v2 = s[f][g][2] * 0.125f + m0a;
                    float v3 = s[f][g][3] * 0.125f + m1a;
                    if (needc) {
                        if (j0 + cb     > rlo) v0 = NEG;
                        if (j0 + cb + 1 > rlo) v1 = NEG;
                        if (j0 + cb     > rhi) v2 = NEG;
                        if (j0 + cb + 1 > rhi) v3 = NEG;
                    }
                    s[f][g][0] = v0; s[f][g][1] = v1; s[f][g][2] = v2; s[f][g][3] = v3;
                }
#pragma unroll
                for (int sub = 0; sub < 2; sub++) {
                    float mx = NEG;
#pragma unroll
                    for (int g = 0; g < 8; g++)
                        mx = fmaxf(mx, fmaxf(s[f][g][2 * sub], s[f][g][2 * sub + 1]));
                    mx = fmaxf(mx, __shfl_xor_sync(0xffffffffu, mx, 1));
                    mx = fmaxf(mx, __shfl_xor_sync(0xffffffffu, mx, 2));
                    float mnew = fmaxf(mrow[f][sub], mx);
                    float c = __expf(mrow[f][sub] - mnew);
                    corr[f][sub] = c;
                    mrow[f][sub] = mnew;
                    lrow[f][sub] *= c;
                }
#pragma unroll
                for (int g = 0; g < 8; g++) {
                    float p0 = __expf(s[f][g][0] - mrow[f][0]);
                    float p1 = __expf(s[f][g][1] - mrow[f][0]);
                    float p2 = __expf(s[f][g][2] - mrow[f][1]);
                    float p3 = __expf(s[f][g][3] - mrow[f][1]);
                    lrow[f][0] += p0 + p1;
                    lrow[f][1] += p2 + p3;
                    ph[f][g][0] = packh2(p0, p1);
                    ph[f][g][1] = packh2(p2, p3);
                }
#pragma unroll
                for (int g = 0; g < 8; g++) {
                    o[f][g][0] *= corr[f][0];
                    o[f][g][1] *= corr[f][0];
                    o[f][g][2] *= corr[f][1];
                    o[f][g][3] *= corr[f][1];
                }
            }

#pragma unroll
            for (int kc = 0; kc < 4; kc++) {
#pragma unroll
                for (int gd = 0; gd < 4; gd++) {
                    uint32_t r0, r1, r2, r3;
                    uint32_t addr = vs_base +
                        ((uint32_t)((kc * 16 + ((lid >> 3) & 1) * 8 + (lid & 7)) * 72 +
                                    gd * 16 + ((lid >> 4) & 1) * 8)) * 2;
                    ldsm_x4_t(addr, r0, r1, r2, r3);
#pragma unroll
                    for (int f = 0; f < 2; f++) {
                        mma16816(o[f][2 * gd], ph[f][2 * kc][0], ph[f][2 * kc][1],
                                 ph[f][2 * kc + 1][0], ph[f][2 * kc + 1][1], r0, r1);
                        mma16816(o[f][2 * gd + 1], ph[f][2 * kc][0], ph[f][2 * kc][1],
                                 ph[f][2 * kc + 1][0], ph[f][2 * kc + 1][1], r2, r3);
                    }
                }
            }
        }
        __syncthreads();
    }

    float inv[2][2];
#pragma unroll
    for (int f = 0; f < 2; f++)
#pragma unroll
        for (int sub = 0; sub < 2; sub++) {
            float lf = lrow[f][sub];
            lf += __shfl_xor_sync(0xffffffffu, lf, 1);
            lf += __shfl_xor_sync(0xffffffffu, lf, 2);
            inv[f][sub] = 1.f / fmaxf(lf, 1e-20f);
        }

#pragma unroll
    for (int f = 0; f < 2; f++) {
        int row = q0 + wm + f * 16 + (lid >> 2);
#pragma unroll
        for (int g = 0; g < 8; g++) {
            __half* yp = y + ((size_t)(b * TT + row)) * CC + h * HD + g * 8 + (lid & 3) * 2;
            *(__half2*)yp = __floats2half2_rn(o[f][g][0] * inv[f][0],
                                              o[f][g][1] * inv[f][0]);
            *(__half2*)(yp + (size_t)8 * CC) = __floats2half2_rn(o[f][g][2] * inv[f][1],
                                                                 o[f][g][3] * inv[f][1]);
        }
    }
}

// ---------------------------------------------------------------------------
extern "C" void kernel_launch(void* const* d_in, const int* in_sizes, int n_in,
                              void* d_out, int out_size)
{
    const float* x  = (const float*)d_in[0];
    const float* Wq = (const float*)d_in[1];
    const float* bq = (const float*)d_in[2];
    const float* Wk = (const float*)d_in[3];
    const float* bk = (const float*)d_in[4];
    const float* Wv = (const float*)d_in[5];
    const float* bv = (const float*)d_in[6];
    const float* Wp = (const float*)d_in[7];
    const float* bp = (const float*)d_in[8];
    const int* mask = (const int*)d_in[9];
    float* out = (float*)d_out;

    __half *qh, *kh, *vh, *yh, *xh, *wqh, *wkh, *wvh, *wph;
    cudaGetSymbolAddress((void**)&qh,  g_qh);
    cudaGetSymbolAddress((void**)&kh,  g_kh);
    cudaGetSymbolAddress((void**)&vh,  g_vh);
    cudaGetSymbolAddress((void**)&yh,  g_yh);
    cudaGetSymbolAddress((void**)&xh,  g_xh);
    cudaGetSymbolAddress((void**)&wqh, g_wqh);
    cudaGetSymbolAddress((void**)&wkh, g_wkh);
    cudaGetSymbolAddress((void**)&wvh, g_wvh);
    cudaGetSymbolAddress((void**)&wph, g_wph);

    cudaFuncSetAttribute(gemm_cp<0>, cudaFuncAttributeMaxDynamicSharedMemorySize,
                         GEMM_SMEM);
    cudaFuncSetAttribute(gemm_cp<1>, cudaFuncAttributeMaxDynamicSharedMemorySize,
                         GEMM_SMEM);

    const int nX = MM * CC;      // 8388608
    const int nW = CC * CC;      // 1048576

    f2h_kernel<<<nX / 1024, 256>>>(x,  xh,  nX);
    f2h_kernel<<<nW / 1024, 256>>>(Wq, wqh, nW);
    f2h_kernel<<<nW / 1024, 256>>>(Wk, wkh, nW);
    f2h_kernel<<<nW / 1024, 256>>>(Wv, wvh, nW);
    f2h_kernel<<<nW / 1024, 256>>>(Wp, wph, nW);

    // fused QKV: one launch, z selects weight/bias/output
    gemm_cp<1><<<dim3(CC / 128, MM / 128, 3), 256, GEMM_SMEM>>>(
        xh, wqh, wkh, wvh, bq, bk, bv, qh, kh, vh, CC);

    attn_mma<<<dim3(TT / 128, BB * HH), 128>>>(qh, kh, vh, mask, yh);

    gemm_cp<0><<<dim3(CC / 128, MM / 128, 1), 256, GEMM_SMEM>>>(
        yh, wph, wph, wph, bp, bp, bp, out, out, out, CC);
}